// round 5
// baseline (speedup 1.0000x reference)
#include <cuda_runtime.h>
#include <cuda_bf16.h>
#include <cstdint>

#define N_NODES 50000
#define N_EDGES 600000
#define HID     128
#define N_GRAPHS 512
#define BN_EPS  1e-5f

// ---------------- scratch (static device allocations; no cudaMalloc) ----------------
__device__ float g_h0[N_NODES * HID];
__device__ float g_h1[N_NODES * HID];
__device__ float g_hbn[N_NODES * HID];
__device__ float g_neigh[N_NODES * HID];
__device__ float g_t2[N_NODES * HID];

__device__ int   g_deg[N_NODES];
__device__ int   g_off[N_NODES + 1];
__device__ int   g_cur[N_NODES];
__device__ int   g_csr[N_EDGES];
__device__ float g_invdeg[N_NODES];

__device__ float g_bnsum[HID];
__device__ float g_bnsq[HID];
__device__ float g_scale[HID];
__device__ float g_shift[HID];

// ---------------- helpers ----------------
__device__ __forceinline__ unsigned long long pack_dup(float x) {
    unsigned long long d;
    asm("mov.b64 %0,{%1,%1};" : "=l"(d) : "f"(x));
    return d;
}

__device__ __forceinline__ uint32_t smem_u32(const void* p) {
    uint32_t a;
    asm("{ .reg .u64 t; cvta.to.shared.u64 t, %1; cvt.u32.u64 %0, t; }" : "=r"(a) : "l"(p));
    return a;
}

#define CP_ASYNC16(dst, src) \
    asm volatile("cp.async.cg.shared.global [%0], [%1], 16;" :: "r"(dst), "l"(src))
#define CP_COMMIT() asm volatile("cp.async.commit_group;" ::: "memory")
#define CP_WAIT0()  asm volatile("cp.async.wait_group 0;" ::: "memory")

// transposed A layout: element (k, row) at k*132 + 4*(k>>2) + row (conflict-free)
#define AS_IDX(k, row) ((k) * 132 + 4 * ((k) >> 2) + (row))
#define AS_SIZE 4256
// B layout: element (k, n) at k*132 + n
#define BS_IDX(k, n) ((k) * 132 + (n))
#define BS_SIZE 4224
#define TS_SIZE 17024

// ---------------- setup kernels ----------------
__global__ void zero_init_kernel() {
    int i = blockIdx.x * blockDim.x + threadIdx.x;
    if (i < N_NODES) g_deg[i] = 0;
    if (i < HID) { g_bnsum[i] = 0.f; g_bnsq[i] = 0.f; }
}

__global__ void hist_kernel(const int* __restrict__ dst) {
    int e = blockIdx.x * blockDim.x + threadIdx.x;
    if (e < N_EDGES) atomicAdd(&g_deg[dst[e]], 1);
}

__global__ void scan_kernel() {
    __shared__ int sh[1024];
    const int CH = (N_NODES + 1023) / 1024;  // 49
    int t = threadIdx.x;
    int base = t * CH;
    int tsum = 0;
    for (int i = 0; i < CH; i++) {
        int idx = base + i;
        if (idx < N_NODES) tsum += g_deg[idx];
    }
    sh[t] = tsum;
    __syncthreads();
    for (int off = 1; off < 1024; off <<= 1) {
        int v = (t >= off) ? sh[t - off] : 0;
        __syncthreads();
        sh[t] += v;
        __syncthreads();
    }
    int run = sh[t] - tsum;
    for (int i = 0; i < CH; i++) {
        int idx = base + i;
        if (idx < N_NODES) {
            int d = g_deg[idx];
            g_off[idx] = run;
            g_cur[idx] = run;
            g_invdeg[idx] = 1.0f / (float)max(d, 1);
            run += d;
        }
    }
    if (t == 1023) g_off[N_NODES] = sh[1023];
}

__global__ void scatter_kernel(const int* __restrict__ src, const int* __restrict__ dst) {
    int e = blockIdx.x * blockDim.x + threadIdx.x;
    if (e < N_EDGES) {
        int d = dst[e];
        int p = atomicAdd(&g_cur[d], 1);
        g_csr[p] = src[e];
    }
}

// ---------------- aggregation kernels (warp per node) ----------------
__global__ void gin_agg_kernel(const float* __restrict__ x) {
    int w = (blockIdx.x * blockDim.x + threadIdx.x) >> 5;
    int lane = threadIdx.x & 31;
    if (w >= N_NODES) return;
    const float4* x4 = (const float4*)x;
    float4 acc = __ldg(&x4[w * 32 + lane]);
    int e = g_off[w], end = g_off[w + 1];
    for (; e + 4 <= end; e += 4) {
        int s0 = g_csr[e + 0], s1 = g_csr[e + 1], s2 = g_csr[e + 2], s3 = g_csr[e + 3];
        float4 v0 = __ldg(&x4[s0 * 32 + lane]);
        float4 v1 = __ldg(&x4[s1 * 32 + lane]);
        float4 v2 = __ldg(&x4[s2 * 32 + lane]);
        float4 v3 = __ldg(&x4[s3 * 32 + lane]);
        acc.x += v0.x + v1.x + v2.x + v3.x;
        acc.y += v0.y + v1.y + v2.y + v3.y;
        acc.z += v0.z + v1.z + v2.z + v3.z;
        acc.w += v0.w + v1.w + v2.w + v3.w;
    }
    for (; e < end; e++) {
        int s0 = g_csr[e];
        float4 v0 = __ldg(&x4[s0 * 32 + lane]);
        acc.x += v0.x; acc.y += v0.y; acc.z += v0.z; acc.w += v0.w;
    }
    ((float4*)g_h0)[w * 32 + lane] = acc;
}

__device__ __forceinline__ float4 bn_relu4(float4 h, float4 sc, float4 sh) {
    float4 r;
    r.x = fmaxf(fmaf(h.x, sc.x, sh.x), 0.f);
    r.y = fmaxf(fmaf(h.y, sc.y, sh.y), 0.f);
    r.z = fmaxf(fmaf(h.z, sc.z, sh.z), 0.f);
    r.w = fmaxf(fmaf(h.w, sc.w, sh.w), 0.f);
    return r;
}

__global__ void sage_agg_kernel(const float* __restrict__ hraw,
                                float* __restrict__ hbn,
                                float* __restrict__ neigh) {
    int w = (blockIdx.x * blockDim.x + threadIdx.x) >> 5;
    int lane = threadIdx.x & 31;
    if (w >= N_NODES) return;
    float4 sc = *(const float4*)&g_scale[lane * 4];
    float4 sh = *(const float4*)&g_shift[lane * 4];
    const float4* h4 = (const float4*)hraw;

    float4 self = bn_relu4(__ldg(&h4[w * 32 + lane]), sc, sh);
    ((float4*)hbn)[w * 32 + lane] = self;

    float4 acc = make_float4(0.f, 0.f, 0.f, 0.f);
    int e = g_off[w], end = g_off[w + 1];
    for (; e + 4 <= end; e += 4) {
        int s0 = g_csr[e + 0], s1 = g_csr[e + 1], s2 = g_csr[e + 2], s3 = g_csr[e + 3];
        float4 v0 = bn_relu4(__ldg(&h4[s0 * 32 + lane]), sc, sh);
        float4 v1 = bn_relu4(__ldg(&h4[s1 * 32 + lane]), sc, sh);
        float4 v2 = bn_relu4(__ldg(&h4[s2 * 32 + lane]), sc, sh);
        float4 v3 = bn_relu4(__ldg(&h4[s3 * 32 + lane]), sc, sh);
        acc.x += v0.x + v1.x + v2.x + v3.x;
        acc.y += v0.y + v1.y + v2.y + v3.y;
        acc.z += v0.z + v1.z + v2.z + v3.z;
        acc.w += v0.w + v1.w + v2.w + v3.w;
    }
    for (; e < end; e++) {
        int s0 = g_csr[e];
        float4 v0 = bn_relu4(__ldg(&h4[s0 * 32 + lane]), sc, sh);
        acc.x += v0.x; acc.y += v0.y; acc.z += v0.z; acc.w += v0.w;
    }
    float id = g_invdeg[w];
    acc.x *= id; acc.y *= id; acc.z *= id; acc.w *= id;
    ((float4*)neigh)[w * 32 + lane] = acc;
}

// ---------------- GEMM building blocks ----------------
// A prefetch into registers (4 x float4 per thread)
__device__ __forceinline__ void ldg_A(const float* __restrict__ A, int rowBase, int kc,
                                      int M, int tid, float4 r[4]) {
#pragma unroll
    for (int i = 0; i < 4; i++) {
        int f = tid + 256 * i;
        int row = f >> 3, kq = f & 7;
        int grow = rowBase + row; if (grow >= M) grow = M - 1;
        r[i] = __ldg((const float4*)&A[grow * HID + kc + kq * 4]);
    }
}

// store prefetched A regs transposed into Asf
__device__ __forceinline__ void sts_A(float* __restrict__ Asf, int tid, const float4 r[4]) {
#pragma unroll
    for (int i = 0; i < 4; i++) {
        int f = tid + 256 * i;
        int row = f >> 3, kq = f & 7;
        int k0 = kq * 4;
        Asf[AS_IDX(k0 + 0, row)] = r[i].x;
        Asf[AS_IDX(k0 + 1, row)] = r[i].y;
        Asf[AS_IDX(k0 + 2, row)] = r[i].z;
        Asf[AS_IDX(k0 + 3, row)] = r[i].w;
    }
}

// stage W chunk [32 k x 128 n] via cp.async (16B, L2-cached)
__device__ __forceinline__ void cp_B(uint32_t bsf, const float* __restrict__ W,
                                     int kc, int tid) {
#pragma unroll
    for (int i = 0; i < 4; i++) {
        int f = tid + 256 * i;
        int k = f >> 5, n4 = f & 31;
        uint32_t dst = bsf + (uint32_t)(BS_IDX(k, n4 * 4)) * 4u;
        CP_ASYNC16(dst, &W[(kc + k) * HID + n4 * 4]);
    }
}

// 32-k compute over staged chunk
__device__ __forceinline__ void compute_chunk(const float* __restrict__ Afrag,
                                              const float* __restrict__ Bsf,
                                              int trow, int tcol,
                                              unsigned long long acc[8][4]) {
#pragma unroll 8
    for (int k = 0; k < 32; k++) {
        const float* ar = &Afrag[k * 132 + 4 * (k >> 2) + trow * 16];
        unsigned long long a[8];
        ulonglong2 t;
        t = *(const ulonglong2*)(ar + 0);  a[0] = t.x; a[1] = t.y;
        t = *(const ulonglong2*)(ar + 4);  a[2] = t.x; a[3] = t.y;
        t = *(const ulonglong2*)(ar + 8);  a[4] = t.x; a[5] = t.y;
        t = *(const ulonglong2*)(ar + 12); a[6] = t.x; a[7] = t.y;
        float4 b4 = *(const float4*)&Bsf[BS_IDX(k, tcol * 4)];
        unsigned long long bb0 = pack_dup(b4.x);
        unsigned long long bb1 = pack_dup(b4.y);
        unsigned long long bb2 = pack_dup(b4.z);
        unsigned long long bb3 = pack_dup(b4.w);
#pragma unroll
        for (int r = 0; r < 8; r++) {
            asm("fma.rn.f32x2 %0,%1,%2,%0;" : "+l"(acc[r][0]) : "l"(a[r]), "l"(bb0));
            asm("fma.rn.f32x2 %0,%1,%2,%0;" : "+l"(acc[r][1]) : "l"(a[r]), "l"(bb1));
            asm("fma.rn.f32x2 %0,%1,%2,%0;" : "+l"(acc[r][2]) : "l"(a[r]), "l"(bb2));
            asm("fma.rn.f32x2 %0,%1,%2,%0;" : "+l"(acc[r][3]) : "l"(a[r]), "l"(bb3));
        }
    }
}

// epilogue: bias (+relu) (+BN stats) + store
__device__ __forceinline__ void gemm_epilogue(unsigned long long acc[8][4],
                                              const float* __restrict__ bias,
                                              float* __restrict__ out,
                                              float* csum, float* csq,
                                              int rowBase, int trow, int tcol,
                                              int M, int do_relu, int do_stats, int tid) {
    float4 bias4 = __ldg((const float4*)&bias[tcol * 4]);
    float bv[4] = { bias4.x, bias4.y, bias4.z, bias4.w };
    float lsum[4] = {0, 0, 0, 0}, lsq[4] = {0, 0, 0, 0};
#pragma unroll
    for (int r = 0; r < 8; r++) {
        float vlo[4], vhi[4];
#pragma unroll
        for (int c = 0; c < 4; c++) {
            unsigned long long u = acc[r][c];
            vlo[c] = __uint_as_float((unsigned)u) + bv[c];
            vhi[c] = __uint_as_float((unsigned)(u >> 32)) + bv[c];
            if (do_relu) { vlo[c] = fmaxf(vlo[c], 0.f); vhi[c] = fmaxf(vhi[c], 0.f); }
        }
        int row0 = rowBase + trow * 16 + 2 * r;
        if (row0 < M) {
            *(float4*)&out[row0 * HID + tcol * 4] = make_float4(vlo[0], vlo[1], vlo[2], vlo[3]);
            if (do_stats)
#pragma unroll
                for (int c = 0; c < 4; c++) { lsum[c] += vlo[c]; lsq[c] += vlo[c] * vlo[c]; }
        }
        if (row0 + 1 < M) {
            *(float4*)&out[(row0 + 1) * HID + tcol * 4] = make_float4(vhi[0], vhi[1], vhi[2], vhi[3]);
            if (do_stats)
#pragma unroll
                for (int c = 0; c < 4; c++) { lsum[c] += vhi[c]; lsq[c] += vhi[c] * vhi[c]; }
        }
    }
    if (do_stats) {
#pragma unroll
        for (int c = 0; c < 4; c++) {
            atomicAdd(&csum[tcol * 4 + c], lsum[c]);
            atomicAdd(&csq[tcol * 4 + c], lsq[c]);
        }
        __syncthreads();
        if (tid < HID) {
            atomicAdd(&g_bnsum[tid], csum[tid]);
            atomicAdd(&g_bnsq[tid], csq[tid]);
        }
    }
}

// ---------------- SAGE GEMM: out = A1@W1 + A2@W2 + bias, stats ----------------
// 8 flat chunks (2 parts x 4), ping-pong buffers, cp.async B + reg-prefetch A
__global__ __launch_bounds__(256, 2) void gemm_sage_kernel(
    const float* __restrict__ A1, const float* __restrict__ W1,
    const float* __restrict__ A2, const float* __restrict__ W2,
    const float* __restrict__ bias, float* __restrict__ out, int M)
{
    extern __shared__ __align__(16) float dyn[];
    float* Abuf[2] = { dyn, dyn + AS_SIZE };
    float* Bbuf[2] = { dyn + 2 * AS_SIZE, dyn + 2 * AS_SIZE + BS_SIZE };
    __shared__ float csum[HID], csq[HID];

    int tid = threadIdx.x;
    int tcol = tid & 31;
    int trow = tid >> 5;
    int rowBase = blockIdx.x * 128;
    uint32_t b_u32[2] = { smem_u32(Bbuf[0]), smem_u32(Bbuf[1]) };

    const float* Aparts[2] = { A1, A2 };
    const float* Wparts[2] = { W1, W2 };

    unsigned long long acc[8][4];
#pragma unroll
    for (int r = 0; r < 8; r++)
#pragma unroll
        for (int c = 0; c < 4; c++) acc[r][c] = 0ULL;
    if (tid < HID) { csum[tid] = 0.f; csq[tid] = 0.f; }

    float4 pf[4];
    // prologue: chunk 0
    ldg_A(Aparts[0], rowBase, 0, M, tid, pf);
    cp_B(b_u32[0], Wparts[0], 0, tid);
    CP_COMMIT();
    sts_A(Abuf[0], tid, pf);
    CP_WAIT0();
    __syncthreads();

#pragma unroll
    for (int cc = 0; cc < 8; cc++) {
        int cur = cc & 1;
        if (cc < 7) {
            int nc = cc + 1;
            int part = nc >> 2, kc = (nc & 3) * 32;
            cp_B(b_u32[nc & 1], Wparts[part], kc, tid);
            CP_COMMIT();
            ldg_A(Aparts[part], rowBase, kc, M, tid, pf);
        }
        compute_chunk(Abuf[cur], Bbuf[cur], trow, tcol, acc);
        if (cc < 7) {
            sts_A(Abuf[cur ^ 1], tid, pf);
            CP_WAIT0();
        }
        __syncthreads();
    }
    gemm_epilogue(acc, bias, out, csum, csq, rowBase, trow, tcol, M, 0, 1, tid);
}

// ---------------- fused GIN MLP: out = relu(A@W1+b1)@W2 + b2 (+stats) ----------------
// phase-1 ping-pong buffers alias into Tsf (Tsf only live from phase-1 epilogue on)
__global__ __launch_bounds__(256, 2) void gin_mlp_fused_kernel(
    const float* __restrict__ A, const float* __restrict__ W1, const float* __restrict__ b1,
    const float* __restrict__ W2, const float* __restrict__ b2,
    float* __restrict__ out, int M)
{
    extern __shared__ __align__(16) float dyn[];
    float* Asf = dyn;                     // AS_SIZE
    float* Bsf = dyn + AS_SIZE;           // BS_SIZE
    float* Tsf = dyn + AS_SIZE + BS_SIZE; // TS_SIZE
    // phase-1 ping-pong second buffers live inside Tsf
    float* Abuf[2] = { Asf, Tsf };
    float* Bbuf[2] = { Bsf, Tsf + AS_SIZE };
    __shared__ float csum[HID], csq[HID];

    int tid = threadIdx.x;
    int tcol = tid & 31;
    int trow = tid >> 5;
    int rowBase = blockIdx.x * 128;
    uint32_t b_u32[2] = { smem_u32(Bbuf[0]), smem_u32(Bbuf[1]) };
    uint32_t bsf_u32 = b_u32[0];
    uint32_t asf_u32 = smem_u32(Asf);

    unsigned long long acc[8][4];
#pragma unroll
    for (int r = 0; r < 8; r++)
#pragma unroll
        for (int c = 0; c < 4; c++) acc[r][c] = 0ULL;
    if (tid < HID) { csum[tid] = 0.f; csq[tid] = 0.f; }

    float4 pf[4];
    // ---- phase 1: t = relu(A @ W1 + b1), ping-pong over 4 chunks ----
    ldg_A(A, rowBase, 0, M, tid, pf);
    cp_B(b_u32[0], W1, 0, tid);
    CP_COMMIT();
    sts_A(Abuf[0], tid, pf);
    CP_WAIT0();
    __syncthreads();

#pragma unroll
    for (int cc = 0; cc < 4; cc++) {
        int cur = cc & 1;
        if (cc < 3) {
            int kc = (cc + 1) * 32;
            cp_B(b_u32[(cc + 1) & 1], W1, kc, tid);
            CP_COMMIT();
            ldg_A(A, rowBase, kc, M, tid, pf);
        }
        compute_chunk(Abuf[cur], Bbuf[cur], trow, tcol, acc);
        if (cc < 3) {
            sts_A(Abuf[cur ^ 1], tid, pf);
            CP_WAIT0();
        }
        __syncthreads();
    }

    // phase-1 epilogue: write t into Tsf (transposed A-frag layout), reset acc
    {
        float4 bias4 = __ldg((const float4*)&b1[tcol * 4]);
        float bv[4] = { bias4.x, bias4.y, bias4.z, bias4.w };
#pragma unroll
        for (int r = 0; r < 8; r++) {
            int row0 = trow * 16 + 2 * r;
#pragma unroll
            for (int c = 0; c < 4; c++) {
                unsigned long long u = acc[r][c];
                float vlo = fmaxf(__uint_as_float((unsigned)u) + bv[c], 0.f);
                float vhi = fmaxf(__uint_as_float((unsigned)(u >> 32)) + bv[c], 0.f);
                int col = tcol * 4 + c;
                Tsf[AS_IDX(col, row0)] = vlo;
                Tsf[AS_IDX(col, row0 + 1)] = vhi;
                acc[r][c] = 0ULL;
            }
        }
    }
    // stage W2 chunk 0 into Bsf (Bsf free: phase-1 compute done)
    cp_B(bsf_u32, W2, 0, tid);
    CP_COMMIT();
    CP_WAIT0();
    __syncthreads();

    // ---- phase 2: out = t @ W2 + b2; B ping-pong {Bsf, Asf}, A from Tsf ----
    uint32_t b2_u32[2] = { bsf_u32, asf_u32 };
    float* B2buf[2] = { Bsf, Asf };
#pragma unroll
    for (int cc = 0; cc < 4; cc++) {
        int cur = cc & 1;
        if (cc < 3) {
            cp_B(b2_u32[(cc + 1) & 1], W2, (cc + 1) * 32, tid);
            CP_COMMIT();
        }
        compute_chunk(&Tsf[cc * 32 * 133], B2buf[cur], trow, tcol, acc);
        if (cc < 3) CP_WAIT0();
        __syncthreads();
    }
    gemm_epilogue(acc, b2, out, csum, csq, rowBase, trow, tcol, M, 0, 1, tid);
}

// ---------------- BN finalize ----------------
__global__ void bn_finalize_kernel(const float* __restrict__ gamma, const float* __restrict__ beta) {
    int c = threadIdx.x;
    const float invn = 1.0f / (float)N_NODES;
    float m = g_bnsum[c] * invn;
    float var = g_bnsq[c] * invn - m * m;
    var = fmaxf(var, 0.f);
    float s = gamma[c] * rsqrtf(var + BN_EPS);
    g_scale[c] = s;
    g_shift[c] = beta[c] - m * s;
    g_bnsum[c] = 0.f;
    g_bnsq[c] = 0.f;
}

// ---------------- pooling: batch is sorted, block per graph ----------------
__device__ __forceinline__ int lbound(const int* a, int n, int v) {
    int lo = 0, hi = n;
    while (lo < hi) {
        int mid = (lo + hi) >> 1;
        if (a[mid] < v) lo = mid + 1; else hi = mid;
    }
    return lo;
}

__global__ void pool_kernel(const float* __restrict__ hraw,
                            const int* __restrict__ batch,
                            float* __restrict__ out) {
    int gg = blockIdx.x;
    int c = threadIdx.x;
    int start = lbound(batch, N_NODES, gg);
    int end = lbound(batch, N_NODES, gg + 1);
    int cnt = end - start;
    float sc = g_scale[c], sh = g_shift[c];
    float s = 0.f;
    for (int i = start; i < end; i++) {
        float v = fmaf(hraw[i * HID + c], sc, sh);
        s += fmaxf(v, 0.f);
    }
    out[gg * HID + c] = s / fmaxf((float)cnt, 1.f);
}

// ---------------- launch ----------------
extern "C" void kernel_launch(void* const* d_in, const int* in_sizes, int n_in,
                              void* d_out, int out_size) {
    (void)in_sizes; (void)n_in; (void)out_size;
    const float* x       = (const float*)d_in[0];
    const int*   eidx    = (const int*)d_in[1];
    const int*   batch   = (const int*)d_in[2];
    const float* gin_w1  = (const float*)d_in[3];
    const float* gin_b1  = (const float*)d_in[4];
    const float* gin_w2  = (const float*)d_in[5];
    const float* gin_b2  = (const float*)d_in[6];
    const float* sage_wl = (const float*)d_in[7];
    const float* sage_bl = (const float*)d_in[8];
    const float* sage_wr = (const float*)d_in[9];
    const float* bn_g    = (const float*)d_in[10];
    const float* bn_b    = (const float*)d_in[11];
    float* out = (float*)d_out;

    const int* src = eidx;
    const int* dst = eidx + N_EDGES;

    float *p_h0, *p_h1, *p_hbn, *p_ng, *p_t2;
    cudaGetSymbolAddress((void**)&p_h0, g_h0);
    cudaGetSymbolAddress((void**)&p_h1, g_h1);
    cudaGetSymbolAddress((void**)&p_hbn, g_hbn);
    cudaGetSymbolAddress((void**)&p_ng, g_neigh);
    cudaGetSymbolAddress((void**)&p_t2, g_t2);

    const int M = N_NODES;
    const int gemmGrid = (M + 127) / 128;            // 391
    const int aggGrid = (N_NODES * 32 + 255) / 256;
    const int edgeGrid = (N_EDGES + 255) / 256;

    const int ginSmem = (AS_SIZE + BS_SIZE + TS_SIZE) * 4;       // ~102KB
    const int sageSmem = (2 * AS_SIZE + 2 * BS_SIZE) * 4;        // ~68KB
    static int attr_set = 0;
    if (!attr_set) {
        cudaFuncSetAttribute(gin_mlp_fused_kernel,
                             cudaFuncAttributeMaxDynamicSharedMemorySize, ginSmem);
        cudaFuncSetAttribute(gemm_sage_kernel,
                             cudaFuncAttributeMaxDynamicSharedMemorySize, sageSmem);
        attr_set = 1;
    }

    // CSR build
    zero_init_kernel<<<(N_NODES + 255) / 256, 256>>>();
    hist_kernel<<<edgeGrid, 256>>>(dst);
    scan_kernel<<<1, 1024>>>();
    scatter_kernel<<<edgeGrid, 256>>>(src, dst);

    // Layer 0: GIN (fused MLP)
    gin_agg_kernel<<<aggGrid, 256>>>(x);
    gin_mlp_fused_kernel<<<gemmGrid, 256, ginSmem>>>(p_h0, gin_w1, gin_b1, gin_w2, gin_b2, p_h1, M);
    bn_finalize_kernel<<<1, HID>>>(bn_g + 0 * HID, bn_b + 0 * HID);

    // SAGE layer 0
    sage_agg_kernel<<<aggGrid, 256>>>(p_h1, p_hbn, p_ng);
    gemm_sage_kernel<<<gemmGrid, 256, sageSmem>>>(p_ng, sage_wl, p_hbn, sage_wr, sage_bl, p_h0, M);
    bn_finalize_kernel<<<1, HID>>>(bn_g + 1 * HID, bn_b + 1 * HID);

    // SAGE layer 1
    sage_agg_kernel<<<aggGrid, 256>>>(p_h0, p_hbn, p_ng);
    gemm_sage_kernel<<<gemmGrid, 256, sageSmem>>>(p_ng, sage_wl + HID * HID, p_hbn,
                                                  sage_wr + HID * HID, sage_bl + HID, p_t2, M);
    bn_finalize_kernel<<<1, HID>>>(bn_g + 2 * HID, bn_b + 2 * HID);

    // global mean pool (batch sorted)
    pool_kernel<<<N_GRAPHS, HID>>>(p_t2, batch, out);
}